// round 3
// baseline (speedup 1.0000x reference)
#include <cuda_runtime.h>
#include <cstdint>
#include <math.h>

// ---------------------------------------------------------------------------
// 2-layer LSTM (B=64, T=2048, D=64, H=512) + linear head + log_softmax.
// Persistent weight-stationary kernel: 128 CTAs, each owns 4 hidden units
// (16 gate rows). W rows live in SMEM as duplicated f32 pairs; inner loop is
// LDG.64 (2 batches) + broadcast LDS.64 + fma.rn.f32x2 (double-rate fp32).
// h is broadcast through global buffers laid out [t][unit][batch]; per-step
// completion via threadfence + atomicAdd counter, consumers spin (all 128
// CTAs are co-resident: 1 CTA/SM due to 149 KB smem, grid < 148).
// ---------------------------------------------------------------------------

namespace {
constexpr int B_    = 64;
constexpr int T_    = 2048;
constexpr int D_    = 64;
constexpr int H_    = 512;
constexpr int OUT_  = 10;
constexpr int NCTA  = 128;
constexpr int NTHR  = 256;
constexpr int ROWS  = 16;              // gate rows per CTA (4 units * 4 gates)
constexpr int KMAX  = H_ + H_;         // 1024 (phase B: [h2_prev ; h1_t])

constexpr size_t SM_WDUP = (size_t)KMAX * ROWS * 8;   // 131072 B
constexpr size_t SM_GP   = (size_t)4 * ROWS * B_ * 4; //  16384 B
constexpr size_t SM_CST  = (size_t)4 * B_ * 4;        //   1024 B
constexpr size_t SM_BIAS = (size_t)ROWS * 4;          //     64 B
constexpr size_t SMEM_BYTES = SM_WDUP + SM_GP + SM_CST + SM_BIAS; // 148544
}

// Scratch (static device allocations — no runtime alloc).
__device__ float g_h1[(size_t)T_ * H_ * B_];   // layer-0 h, [t][unit][b]
__device__ float g_h2[(size_t)T_ * H_ * B_];   // layer-1 h, [t][unit][b]
__device__ float g_xT[(size_t)T_ * D_ * B_];   // x transposed, [t][k][b]
__device__ int   g_cnt[2 * T_];                // per-step arrival counters

__device__ __forceinline__ void ffma2(uint64_t& acc, uint64_t a, uint64_t b) {
    asm("fma.rn.f32x2 %0, %1, %2, %0;" : "+l"(acc) : "l"(a), "l"(b));
}

__global__ void zero_cnt_kernel() {
    int i = blockIdx.x * blockDim.x + threadIdx.x;
    if (i < 2 * T_) g_cnt[i] = 0;
}

// x[b][t][k] -> g_xT[t][k][b], one 64x64 tile per block via smem.
__global__ void transpose_x_kernel(const float* __restrict__ x) {
    __shared__ float tile[64][65];
    int t = blockIdx.x;
    for (int i = threadIdx.x; i < 64 * 64; i += blockDim.x) {
        int b = i >> 6, k = i & 63;
        tile[b][k] = x[(size_t)b * T_ * D_ + (size_t)t * D_ + k];
    }
    __syncthreads();
    for (int i = threadIdx.x; i < 64 * 64; i += blockDim.x) {
        int k = i >> 6, b = i & 63;
        g_xT[(size_t)t * D_ * B_ + (size_t)k * B_ + b] = tile[b][k];
    }
}

__global__ __launch_bounds__(NTHR, 1)
void lstm_kernel(const float* __restrict__ Wih0, const float* __restrict__ Whh0,
                 const float* __restrict__ bih0, const float* __restrict__ bhh0,
                 const float* __restrict__ Wih1, const float* __restrict__ Whh1,
                 const float* __restrict__ bih1, const float* __restrict__ bhh1) {
    extern __shared__ unsigned char smem[];
    uint64_t* wdup = (uint64_t*)smem;                               // [K][16] dup pairs
    float*    gp   = (float*)(smem + SM_WDUP);                      // [4][16][64] partials
    float*    cst  = (float*)(smem + SM_WDUP + SM_GP);              // [4][64] cell state
    float*    bias = (float*)(smem + SM_WDUP + SM_GP + SM_CST);     // [16]

    const int tid  = threadIdx.x;
    const int lane = tid & 31;
    const int w    = tid >> 5;
    const int rg   = w & 1;        // row-group: rows rg*8 .. rg*8+7
    const int ks   = w >> 1;       // k-split: 0..3
    const int j0   = blockIdx.x * 4;

    volatile int* vcnt = g_cnt;

    for (int phase = 0; phase < 2; ++phase) {
        const float* Whh = phase ? Whh1 : Whh0;
        const float* Wih = phase ? Wih1 : Wih0;
        const float* bih = phase ? bih1 : bih0;
        const float* bhh = phase ? bhh1 : bhh0;
        const int    K2  = phase ? H_ : D_;            // feed-forward K
        float*       hout = phase ? g_h2 : g_h1;
        const float* rin  = phase ? g_h2 : g_h1;       // recurrent input (t-1)
        const float* xin  = phase ? g_h1 : g_xT;       // feed-forward input (t)
        const int    xstride = K2 * B_;

        // ---- load weights: rows 0..511 = W_hh, 512.. = W_ih, duplicated ----
        for (int idx = tid; idx < (H_ + K2) * ROWS; idx += NTHR) {
            int k = idx / ROWS;
            int r = idx - k * ROWS;
            int gate = r >> 2, j = r & 3;
            int row = gate * H_ + j0 + j;
            float wv = (k < H_) ? Whh[(size_t)row * H_ + k]
                                : Wih[(size_t)row * K2 + (k - H_)];
            uint32_t wb = __float_as_uint(wv);
            wdup[(size_t)k * ROWS + r] = ((uint64_t)wb << 32) | wb;
        }
        if (tid < ROWS) {
            int gate = tid >> 2, j = tid & 3;
            int row = gate * H_ + j0 + j;
            bias[tid] = bih[row] + bhh[row];
        }
        cst[tid] = 0.f;  // exactly 256 entries
        __syncthreads();

        const int cbase = phase * T_;

        for (int t = 0; t < T_; ++t) {
            // ---- wait for dependencies ----
            if (tid == 0) {
                if (phase == 1) { while (vcnt[t] < NCTA) {} }          // layer-0 h[t]
                if (t > 0)      { while (vcnt[cbase + t - 1] < NCTA) {} } // own h[t-1]
            }
            __syncthreads();

            uint64_t acc[8];
            #pragma unroll
            for (int i = 0; i < 8; ++i) acc[i] = 0ull;

            // ---- recurrent part: K = 512 (skip at t=0, state is zero) ----
            if (t > 0) {
                const uint64_t* ip =
                    (const uint64_t*)(rin + (size_t)(t - 1) * H_ * B_) + lane;
                const uint64_t* wd = wdup + rg * 8;
                int kb = ks * (H_ / 4), ke = kb + (H_ / 4);
                #pragma unroll 4
                for (int k = kb; k < ke; ++k) {
                    uint64_t in2 = ip[(size_t)k * (B_ / 2)];
                    const uint64_t* wr = wd + (size_t)k * ROWS;
                    #pragma unroll
                    for (int i = 0; i < 8; ++i) ffma2(acc[i], wr[i], in2);
                }
            }
            // ---- feed-forward part: K = K2, weight rows offset by H_ ----
            {
                const uint64_t* ip =
                    (const uint64_t*)(xin + (size_t)t * xstride) + lane;
                const uint64_t* wd = wdup + (size_t)H_ * ROWS + rg * 8;
                int kb = ks * (K2 / 4), ke = kb + (K2 / 4);
                #pragma unroll 4
                for (int k = kb; k < ke; ++k) {
                    uint64_t in2 = ip[(size_t)k * (B_ / 2)];
                    const uint64_t* wr = wd + (size_t)k * ROWS;
                    #pragma unroll
                    for (int i = 0; i < 8; ++i) ffma2(acc[i], wr[i], in2);
                }
            }

            // ---- store partial sums: gp[ks][row][batch] ----
            {
                uint64_t* gp2 = (uint64_t*)gp;
                #pragma unroll
                for (int i = 0; i < 8; ++i)
                    gp2[(size_t)(ks * ROWS + rg * 8 + i) * (B_ / 2) + lane] = acc[i];
            }
            __syncthreads();

            // ---- gates + state update: thread = (j, b) ----
            {
                int j = tid >> 6, b = tid & 63;
                float gi = bias[j],     gf = bias[4 + j];
                float gc = bias[8 + j], go = bias[12 + j];
                #pragma unroll
                for (int s = 0; s < 4; ++s) {
                    gi += gp[(s * ROWS + j)      * B_ + b];
                    gf += gp[(s * ROWS + 4 + j)  * B_ + b];
                    gc += gp[(s * ROWS + 8 + j)  * B_ + b];
                    go += gp[(s * ROWS + 12 + j) * B_ + b];
                }
                float si = 1.f / (1.f + expf(-gi));
                float sf = 1.f / (1.f + expf(-gf));
                float so = 1.f / (1.f + expf(-go));
                float tg = tanhf(gc);
                float c  = sf * cst[tid] + si * tg;
                cst[tid] = c;
                float h  = so * tanhf(c);
                hout[(size_t)t * H_ * B_ + (size_t)(j0 + j) * B_ + b] = h;
            }
            __syncthreads();

            // ---- publish this step's slice ----
            if (tid == 0) {
                __threadfence();
                atomicAdd(&g_cnt[cbase + t], 1);
            }
        }
        __syncthreads();
    }
}

// logits = h2[:, T-1] @ W_lin^T + b_lin ; out = log_softmax(logits)
__global__ void head_kernel(const float* __restrict__ Wlin,
                            const float* __restrict__ blin,
                            float* __restrict__ out) {
    __shared__ float logits[B_ * OUT_];
    __shared__ float lse[B_];
    int tid = threadIdx.x;                 // blockDim = 640 = B_*OUT_
    int b = tid / OUT_, o = tid % OUT_;
    const float* hlast = g_h2 + (size_t)(T_ - 1) * H_ * B_;
    float s = blin[o];
    for (int k = 0; k < H_; ++k)
        s += hlast[(size_t)k * B_ + b] * Wlin[(size_t)o * H_ + k];
    logits[tid] = s;
    __syncthreads();
    if (tid < B_) {
        float m = -1e30f;
        for (int q = 0; q < OUT_; ++q) m = fmaxf(m, logits[tid * OUT_ + q]);
        float z = 0.f;
        for (int q = 0; q < OUT_; ++q) z += expf(logits[tid * OUT_ + q] - m);
        lse[tid] = m + logf(z);
    }
    __syncthreads();
    out[tid] = logits[tid] - lse[b];
}

extern "C" void kernel_launch(void* const* d_in, const int* in_sizes, int n_in,
                              void* d_out, int out_size) {
    const float* x    = (const float*)d_in[0];
    const float* Wih0 = (const float*)d_in[1];
    const float* Whh0 = (const float*)d_in[2];
    const float* bih0 = (const float*)d_in[3];
    const float* bhh0 = (const float*)d_in[4];
    const float* Wih1 = (const float*)d_in[5];
    const float* Whh1 = (const float*)d_in[6];
    const float* bih1 = (const float*)d_in[7];
    const float* bhh1 = (const float*)d_in[8];
    const float* Wlin = (const float*)d_in[9];
    const float* blin = (const float*)d_in[10];
    float* out = (float*)d_out;

    cudaFuncSetAttribute(lstm_kernel,
                         cudaFuncAttributeMaxDynamicSharedMemorySize,
                         (int)SMEM_BYTES);

    zero_cnt_kernel<<<(2 * T_ + 255) / 256, 256>>>();
    transpose_x_kernel<<<T_, 256>>>(x);
    lstm_kernel<<<NCTA, NTHR, SMEM_BYTES>>>(Wih0, Whh0, bih0, bhh0,
                                            Wih1, Whh1, bih1, bhh1);
    head_kernel<<<1, B_ * OUT_>>>(Wlin, blin, out);
}

// round 4
// speedup vs baseline: 2.1322x; 2.1322x over previous
#include <cuda_runtime.h>
#include <cstdint>
#include <math.h>

// ---------------------------------------------------------------------------
// 2-layer LSTM (B=64, T=2048, D=64, H=512) + linear head + log_softmax.
//
// Persistent weight-stationary kernel, BOTH layers pipelined in one pass:
// round r computes layer0 step r and layer1 step r-1, then ONE global
// barrier (fence + atomicAdd counter, consumers spin). 2049 rounds total.
//
// Each CTA owns 4 hidden units per layer (16 gate rows/layer). Weights live
// in SMEM un-duplicated as [k][16]; LDS.128 gives two row-pairs, the batch
// input is duplicated into an f32x2 register, and fma.rn.f32x2 (FFMA2,
// double-rate fp32) accumulates row-pairs. 512 threads = 16 warps
// (batch-half x 8 k-slices) for LDG latency hiding.
// ---------------------------------------------------------------------------

namespace {
constexpr int B_   = 64;
constexpr int T_   = 2048;
constexpr int D_   = 64;
constexpr int H_   = 512;
constexpr int OUT_ = 10;
constexpr int NCTA = 128;
constexpr int NTHR = 512;
constexpr int ROWS = 16;             // gate rows per layer per CTA
constexpr int K0   = H_ + D_;        // 576  (layer0: [h1_prev ; x])
constexpr int K1   = H_ + H_;        // 1024 (layer1: [h2_prev ; h1_t])

constexpr size_t OFF_W0  = 0;
constexpr size_t OFF_W1  = OFF_W0 + (size_t)K0 * ROWS * 4;     //  36864
constexpr size_t OFF_GP  = OFF_W1 + (size_t)K1 * ROWS * 4;     // 102400
constexpr size_t OFF_GPR = OFF_GP + (size_t)2 * 8 * 8 * B_ * 8; // +65536
constexpr size_t OFF_CST = OFF_GPR + (size_t)2 * 8 * B_ * 8;    //  +8192
constexpr size_t OFF_BIA = OFF_CST + (size_t)2 * 256 * 4;       //  +2048
constexpr size_t SMEM_BYTES = OFF_BIA + 2 * ROWS * 4;           // 178432
}

// Static device scratch (no runtime allocation).
__device__ float g_h1[(size_t)T_ * H_ * B_];   // layer0 h, [t][unit][b]
__device__ float g_h2[(size_t)T_ * H_ * B_];   // layer1 h, [t][unit][b]
__device__ float g_xT[(size_t)T_ * D_ * B_];   // x transposed, [t][k][b]
__device__ int   g_cnt[T_ + 1];                // per-round arrival counters

__device__ __forceinline__ void ffma2(uint64_t& acc, uint64_t a, uint64_t b) {
    asm("fma.rn.f32x2 %0, %1, %2, %0;" : "+l"(acc) : "l"(a), "l"(b));
}
__device__ __forceinline__ void addf2(uint64_t& acc, uint64_t a) {
    asm("add.rn.f32x2 %0, %0, %1;" : "+l"(acc) : "l"(a));
}
__device__ __forceinline__ uint64_t dup2(float x) {
    uint64_t r;
    asm("mov.b64 %0, {%1, %1};" : "=l"(r) : "f"(x));
    return r;
}

__device__ __forceinline__ float fast_sigmoid(float x) {
    return 1.f / (1.f + __expf(-x));     // x<<0: exp->inf -> 0 (safe)
}
__device__ __forceinline__ float fast_tanh(float x) {
    float a = fabsf(x);
    float t = __expf(-2.f * a);          // t in (0,1], no overflow
    float r = (1.f - t) / (1.f + t);
    return copysignf(r, x);
}

// GEMV slice: acc[i] += W[k][2i..2i+1] * dup(in[k][bcol]) for k in [kb,ke)
__device__ __forceinline__ void gemv(uint64_t acc[8],
                                     const float* __restrict__ wsm,
                                     const float* __restrict__ in,
                                     int kb, int ke, int bcol) {
    const float* ip = in + bcol;
#pragma unroll 8
    for (int k = kb; k < ke; ++k) {
        uint64_t xx = dup2(ip[k * B_]);
        const ulonglong2* wv = (const ulonglong2*)(wsm + k * ROWS);
#pragma unroll
        for (int q = 0; q < 4; ++q) {
            ulonglong2 wp = wv[q];
            ffma2(acc[2 * q],     wp.x, xx);
            ffma2(acc[2 * q + 1], wp.y, xx);
        }
    }
}

__global__ void zero_cnt_kernel() {
    int i = blockIdx.x * blockDim.x + threadIdx.x;
    if (i < T_ + 1) g_cnt[i] = 0;
}

// x[b][t][k] -> g_xT[t][k][b]
__global__ void transpose_x_kernel(const float* __restrict__ x) {
    __shared__ float tile[64][65];
    int t = blockIdx.x;
    for (int i = threadIdx.x; i < 64 * 64; i += blockDim.x) {
        int b = i >> 6, k = i & 63;
        tile[b][k] = x[(size_t)b * T_ * D_ + (size_t)t * D_ + k];
    }
    __syncthreads();
    for (int i = threadIdx.x; i < 64 * 64; i += blockDim.x) {
        int k = i >> 6, b = i & 63;
        g_xT[(size_t)t * D_ * B_ + (size_t)k * B_ + b] = tile[b][k];
    }
}

__global__ __launch_bounds__(NTHR, 1)
void lstm_kernel(const float* __restrict__ Wih0, const float* __restrict__ Whh0,
                 const float* __restrict__ bih0, const float* __restrict__ bhh0,
                 const float* __restrict__ Wih1, const float* __restrict__ Whh1,
                 const float* __restrict__ bih1, const float* __restrict__ bhh1) {
    extern __shared__ unsigned char smem[];
    float*    w0   = (float*)(smem + OFF_W0);      // [K0][16]
    float*    w1   = (float*)(smem + OFF_W1);      // [K1][16]
    uint64_t* gp   = (uint64_t*)(smem + OFF_GP);   // [2][8 ks][8 i][64 b]
    uint64_t* gpr  = (uint64_t*)(smem + OFF_GPR);  // [2][8 i][64 b]
    float*    cst  = (float*)(smem + OFF_CST);     // [2][256]
    float*    bias = (float*)(smem + OFF_BIA);     // [2][16]

    const int tid  = threadIdx.x;
    const int lane = tid & 31;
    const int wid  = tid >> 5;
    const int bh   = wid & 1;                      // batch half
    const int ks   = wid >> 1;                     // k-slice 0..7
    const int bcol = bh * 32 + lane;
    const int j0   = blockIdx.x * 4;

    // ---- load weights (row r = gate*4 + j; k<H_ -> W_hh else W_ih) ----
    for (int idx = tid; idx < K0 * ROWS; idx += NTHR) {
        int k = idx >> 4, r = idx & 15;
        int row = (r >> 2) * H_ + j0 + (r & 3);
        w0[idx] = (k < H_) ? Whh0[(size_t)row * H_ + k]
                           : Wih0[(size_t)row * D_ + (k - H_)];
    }
    for (int idx = tid; idx < K1 * ROWS; idx += NTHR) {
        int k = idx >> 4, r = idx & 15;
        int row = (r >> 2) * H_ + j0 + (r & 3);
        w1[idx] = (k < H_) ? Whh1[(size_t)row * H_ + k]
                           : Wih1[(size_t)row * H_ + (k - H_)];
    }
    if (tid < 32) {
        int l = tid >> 4, r = tid & 15;
        int row = (r >> 2) * H_ + j0 + (r & 3);
        bias[tid] = l ? (bih1[row] + bhh1[row]) : (bih0[row] + bhh0[row]);
    }
    cst[tid] = 0.f;                                // exactly 512 entries
    __syncthreads();

    volatile int* vcnt = g_cnt;

    for (int r = 0; r <= T_; ++r) {
        if (r > 0) {
            if (tid == 0) { while (vcnt[r - 1] < NCTA) {} }
            __syncthreads();
        }

        uint64_t a0[8], a1[8];
#pragma unroll
        for (int i = 0; i < 8; ++i) { a0[i] = 0ull; a1[i] = 0ull; }

        // ---- layer0, step t0 = r ----
        if (r < T_) {
            if (r > 0)
                gemv(a0, w0, g_h1 + (size_t)(r - 1) * H_ * B_,
                     ks * 64, ks * 64 + 64, bcol);          // recurrent K=512
            gemv(a0, w0 + (size_t)H_ * ROWS,
                 g_xT + (size_t)r * D_ * B_,
                 ks * 8, ks * 8 + 8, bcol);                 // feed-fwd K=64
        }
        // ---- layer1, step t1 = r-1 ----
        if (r >= 1) {
            if (r >= 2)
                gemv(a1, w1, g_h2 + (size_t)(r - 2) * H_ * B_,
                     ks * 64, ks * 64 + 64, bcol);          // recurrent K=512
            gemv(a1, w1 + (size_t)H_ * ROWS,
                 g_h1 + (size_t)(r - 1) * H_ * B_,
                 ks * 64, ks * 64 + 64, bcol);              // feed-fwd K=512
        }

        // ---- store partials ----
#pragma unroll
        for (int i = 0; i < 8; ++i) {
            gp[((size_t)(0 * 8 + ks) * 8 + i) * B_ + bcol] = a0[i];
            gp[((size_t)(1 * 8 + ks) * 8 + i) * B_ + bcol] = a1[i];
        }
        __syncthreads();

        // ---- stage 1: reduce 8 k-slices (f32x2 adds) ----
        {
            int i2 = tid >> 6, b = tid & 63;
#pragma unroll
            for (int l = 0; l < 2; ++l) {
                uint64_t s = gp[((size_t)(l * 8 + 0) * 8 + i2) * B_ + b];
#pragma unroll
                for (int s8 = 1; s8 < 8; ++s8)
                    addf2(s, gp[((size_t)(l * 8 + s8) * 8 + i2) * B_ + b]);
                gpr[(size_t)(l * 8 + i2) * B_ + b] = s;
            }
        }
        __syncthreads();

        // ---- stage 2: gates + state update. tid -> (layer, unit j, batch b)
        {
            int l = tid >> 8, item = tid & 255;
            int j = item >> 6, b = item & 63;
            bool active = l ? (r >= 1) : (r < T_);
            if (active) {
                const float* gf32 = (const float*)gpr;
                // row -> (pair i = row>>1, sub = row&1); rows j,4+j,8+j,12+j
                float gi = bias[l * 16 + j] +
                           gf32[(((size_t)l * 8 + (j >> 1)) * B_ + b) * 2 + (j & 1)];
                int rf = 4 + j, rg = 8 + j, ro = 12 + j;
                float gfv = bias[l * 16 + rf] +
                            gf32[(((size_t)l * 8 + (rf >> 1)) * B_ + b) * 2 + (rf & 1)];
                float ggv = bias[l * 16 + rg] +
                            gf32[(((size_t)l * 8 + (rg >> 1)) * B_ + b) * 2 + (rg & 1)];
                float gov = bias[l * 16 + ro] +
                            gf32[(((size_t)l * 8 + (ro >> 1)) * B_ + b) * 2 + (ro & 1)];
                float si = fast_sigmoid(gi);
                float sf = fast_sigmoid(gfv);
                float so = fast_sigmoid(gov);
                float tg = fast_tanh(ggv);
                float c  = sf * cst[tid] + si * tg;
                cst[tid] = c;
                float h  = so * fast_tanh(c);
                int t = l ? (r - 1) : r;
                float* hout = l ? g_h2 : g_h1;
                hout[(size_t)t * H_ * B_ + (size_t)(j0 + j) * B_ + b] = h;
            }
        }
        __syncthreads();

        // ---- publish round r ----
        if (tid == 0) {
            __threadfence();
            atomicAdd(&g_cnt[r], 1);
        }
    }
}

// logits = h2[:, T-1] @ W_lin^T + b_lin ; out = log_softmax
__global__ void head_kernel(const float* __restrict__ Wlin,
                            const float* __restrict__ blin,
                            float* __restrict__ out) {
    __shared__ float hv[H_];
    __shared__ float lg[OUT_];
    int b = blockIdx.x;
    const float* hlast = g_h2 + (size_t)(T_ - 1) * H_ * B_;
    for (int k = threadIdx.x; k < H_; k += blockDim.x)
        hv[k] = hlast[(size_t)k * B_ + b];
    __syncthreads();
    int w = threadIdx.x >> 5, lane = threadIdx.x & 31;
    if (w < OUT_) {
        float s = 0.f;
        for (int k = lane; k < H_; k += 32)
            s += hv[k] * Wlin[(size_t)w * H_ + k];
#pragma unroll
        for (int off = 16; off; off >>= 1)
            s += __shfl_xor_sync(0xffffffffu, s, off);
        if (lane == 0) lg[w] = s + blin[w];
    }
    __syncthreads();
    if (threadIdx.x == 0) {
        float m = -1e30f;
        for (int q = 0; q < OUT_; ++q) m = fmaxf(m, lg[q]);
        float z = 0.f;
        for (int q = 0; q < OUT_; ++q) z += expf(lg[q] - m);
        float lse = m + logf(z);
        for (int q = 0; q < OUT_; ++q) out[b * OUT_ + q] = lg[q] - lse;
    }
}

extern "C" void kernel_launch(void* const* d_in, const int* in_sizes, int n_in,
                              void* d_out, int out_size) {
    const float* x    = (const float*)d_in[0];
    const float* Wih0 = (const float*)d_in[1];
    const float* Whh0 = (const float*)d_in[2];
    const float* bih0 = (const float*)d_in[3];
    const float* bhh0 = (const float*)d_in[4];
    const float* Wih1 = (const float*)d_in[5];
    const float* Whh1 = (const float*)d_in[6];
    const float* bih1 = (const float*)d_in[7];
    const float* bhh1 = (const float*)d_in[8];
    const float* Wlin = (const float*)d_in[9];
    const float* blin = (const float*)d_in[10];
    float* out = (float*)d_out;

    cudaFuncSetAttribute(lstm_kernel,
                         cudaFuncAttributeMaxDynamicSharedMemorySize,
                         (int)SMEM_BYTES);

    zero_cnt_kernel<<<(T_ + 1 + 255) / 256, 256>>>();
    transpose_x_kernel<<<T_, 256>>>(x);
    lstm_kernel<<<NCTA, NTHR, SMEM_BYTES>>>(Wih0, Whh0, bih0, bhh0,
                                            Wih1, Whh1, bih1, bhh1);
    head_kernel<<<B_, 320>>>(Wlin, blin, out);
}

// round 5
// speedup vs baseline: 2.1736x; 1.0194x over previous
#include <cuda_runtime.h>
#include <cstdint>
#include <math.h>

// ---------------------------------------------------------------------------
// 2-layer LSTM (B=64, T=2048, D=64, H=512) + linear head + log_softmax.
//
// Persistent weight-stationary kernel, both layers pipelined: round r computes
// layer0 step r and layer1 step r-1, then ONE global barrier. 2049 rounds.
// Layer0-recurrent and layer1-feedforward share the same input vector
// h1[r-1], so their GEMVs are fused on a single load. The x-feedforward slice
// for the NEXT round is computed during the barrier spin (it has no
// cross-round dependence). Head (linear + log_softmax) runs on CTA 0 after
// the final round. Two kernels total: prep (zero flags + transpose x), lstm.
// ---------------------------------------------------------------------------

namespace {
constexpr int B_   = 64;
constexpr int T_   = 2048;
constexpr int D_   = 64;
constexpr int H_   = 512;
constexpr int OUT_ = 10;
constexpr int NCTA = 128;
constexpr int NTHR = 512;
constexpr int ROWS = 16;                  // gate rows per layer per CTA
constexpr int K0   = H_ + D_;             // layer0: [h1_prev ; x]
constexpr int K1   = H_ + H_;             // layer1: [h2_prev ; h1_t]

constexpr size_t OFF_W0  = 0;                                  // [K0][16] f32
constexpr size_t OFF_W1  = OFF_W0 + (size_t)K0 * ROWS * 4;     //  36864
constexpr size_t OFF_GP  = OFF_W1 + (size_t)K1 * ROWS * 4;     // 102400
constexpr size_t OFF_CST = OFF_GP + (size_t)2 * 8 * 8 * B_ * 8; // 167936
constexpr size_t OFF_BIA = OFF_CST + 2048;                      // 169984
constexpr size_t SMEM_BYTES = OFF_BIA + 128;                    // 170112

constexpr int HV_STRIDE = 521;                 // head staging, bank-friendly
constexpr size_t OFF_LG = (size_t)B_ * HV_STRIDE * 4;           // 133376
}

// Static device scratch (no runtime allocation).
__device__ float g_h1[(size_t)T_ * H_ * B_];   // layer0 h, [t][unit][b]
__device__ float g_h2[(size_t)T_ * H_ * B_];   // layer1 h, [t][unit][b]
__device__ float g_xT[(size_t)T_ * D_ * B_];   // x transposed, [t][k][b]
__device__ int   g_cnt[T_ + 1];                // per-round arrival counters

__device__ __forceinline__ void ffma2(uint64_t& acc, uint64_t a, uint64_t b) {
    asm("fma.rn.f32x2 %0, %1, %2, %0;" : "+l"(acc) : "l"(a), "l"(b));
}
__device__ __forceinline__ void addf2(uint64_t& acc, uint64_t a) {
    asm("add.rn.f32x2 %0, %0, %1;" : "+l"(acc) : "l"(a));
}
__device__ __forceinline__ uint64_t dup2(float x) {
    uint64_t r;
    asm("mov.b64 %0, {%1, %1};" : "=l"(r) : "f"(x));
    return r;
}
__device__ __forceinline__ float2 unpk(uint64_t v) {
    float2 f;
    asm("mov.b64 {%0, %1}, %2;" : "=f"(f.x), "=f"(f.y) : "l"(v));
    return f;
}
__device__ __forceinline__ int ld_acq(const int* p) {
    int v;
    asm volatile("ld.global.acquire.gpu.b32 %0, [%1];" : "=r"(v) : "l"(p));
    return v;
}

__device__ __forceinline__ float fast_sigmoid(float x) {
    return 1.f / (1.f + __expf(-x));
}
__device__ __forceinline__ float fast_tanh(float x) {
    float a = fabsf(x);
    float t = __expf(-2.f * a);
    float r = (1.f - t) / (1.f + t);
    return copysignf(r, x);
}

// acc[i] += W[k][2i..2i+1] * dup(in[k][bcol]), k in [kb,ke)
__device__ __forceinline__ void gemv1(uint64_t a[8], const float* __restrict__ w,
                                      const float* __restrict__ in,
                                      int kb, int ke, int bcol) {
    const float* ip = in + bcol;
#pragma unroll 8
    for (int k = kb; k < ke; ++k) {
        uint64_t xx = dup2(ip[(size_t)k * B_]);
        const ulonglong2* wv = (const ulonglong2*)(w + (size_t)k * ROWS);
#pragma unroll
        for (int q = 0; q < 4; ++q) {
            ulonglong2 wp = wv[q];
            ffma2(a[2 * q],     wp.x, xx);
            ffma2(a[2 * q + 1], wp.y, xx);
        }
    }
}

// Shared-input double GEMV: one load feeds both accumulator sets.
__device__ __forceinline__ void gemv_pair(uint64_t a0[8], uint64_t a1[8],
                                          const float* __restrict__ w0k,
                                          const float* __restrict__ w1k,
                                          const float* __restrict__ in,
                                          int kb, int ke, int bcol) {
    const float* ip = in + bcol;
#pragma unroll 4
    for (int k = kb; k < ke; ++k) {
        uint64_t xx = dup2(ip[(size_t)k * B_]);
        const ulonglong2* v0 = (const ulonglong2*)(w0k + (size_t)k * ROWS);
        const ulonglong2* v1 = (const ulonglong2*)(w1k + (size_t)k * ROWS);
#pragma unroll
        for (int q = 0; q < 4; ++q) {
            ulonglong2 p = v0[q];
            ffma2(a0[2 * q],     p.x, xx);
            ffma2(a0[2 * q + 1], p.y, xx);
        }
#pragma unroll
        for (int q = 0; q < 4; ++q) {
            ulonglong2 p = v1[q];
            ffma2(a1[2 * q],     p.x, xx);
            ffma2(a1[2 * q + 1], p.y, xx);
        }
    }
}

// prep: zero round counters + transpose x[b][t][k] -> g_xT[t][k][b]
__global__ void prep_kernel(const float* __restrict__ x) {
    __shared__ float tile[64][65];
    int t = blockIdx.x;
    if (threadIdx.x == 0) {
        g_cnt[t] = 0;
        if (t == 0) g_cnt[T_] = 0;
    }
    for (int i = threadIdx.x; i < 64 * 64; i += blockDim.x) {
        int b = i >> 6, k = i & 63;
        tile[b][k] = x[(size_t)b * T_ * D_ + (size_t)t * D_ + k];
    }
    __syncthreads();
    for (int i = threadIdx.x; i < 64 * 64; i += blockDim.x) {
        int k = i >> 6, b = i & 63;
        g_xT[(size_t)t * D_ * B_ + (size_t)k * B_ + b] = tile[b][k];
    }
}

__global__ __launch_bounds__(NTHR, 1)
void lstm_kernel(const float* __restrict__ Wih0, const float* __restrict__ Whh0,
                 const float* __restrict__ bih0, const float* __restrict__ bhh0,
                 const float* __restrict__ Wih1, const float* __restrict__ Whh1,
                 const float* __restrict__ bih1, const float* __restrict__ bhh1,
                 const float* __restrict__ Wlin, const float* __restrict__ blin,
                 float* __restrict__ out) {
    extern __shared__ unsigned char smem[];
    float*    w0   = (float*)(smem + OFF_W0);      // [K0][16]
    float*    w1   = (float*)(smem + OFF_W1);      // [K1][16]
    uint64_t* gp   = (uint64_t*)(smem + OFF_GP);   // [2][8 ks][8 pair][64 b]
    float*    cst  = (float*)(smem + OFF_CST);     // [2][4][64]
    float*    bias = (float*)(smem + OFF_BIA);     // [2][16]

    const int tid  = threadIdx.x;
    const int lane = tid & 31;
    const int wid  = tid >> 5;
    const int bh   = wid & 1;                      // batch half
    const int ks   = wid >> 1;                     // k-slice 0..7
    const int bcol = bh * 32 + lane;
    const int j0   = blockIdx.x * 4;

    // ---- load weights (row r = gate*4 + j; k<H_ -> W_hh else W_ih) ----
    for (int idx = tid; idx < K0 * ROWS; idx += NTHR) {
        int k = idx >> 4, r = idx & 15;
        int row = (r >> 2) * H_ + j0 + (r & 3);
        w0[idx] = (k < H_) ? Whh0[(size_t)row * H_ + k]
                           : Wih0[(size_t)row * D_ + (k - H_)];
    }
    for (int idx = tid; idx < K1 * ROWS; idx += NTHR) {
        int k = idx >> 4, r = idx & 15;
        int row = (r >> 2) * H_ + j0 + (r & 3);
        w1[idx] = (k < H_) ? Whh1[(size_t)row * H_ + k]
                           : Wih1[(size_t)row * H_ + (k - H_)];
    }
    if (tid < 32) {
        int l = tid >> 4, r = tid & 15;
        int row = (r >> 2) * H_ + j0 + (r & 3);
        bias[tid] = l ? (bih1[row] + bhh1[row]) : (bih0[row] + bhh0[row]);
    }
    cst[tid & 511] = 0.f;                          // 512 entries
    __syncthreads();

    const float* w0x  = w0 + (size_t)H_ * ROWS;    // layer0 x-ff weights
    const float* w1ff = w1 + (size_t)H_ * ROWS;    // layer1 h1-ff weights

    // x-feedforward slice for round 0 (no cross-CTA dependence)
    uint64_t ax[8];
#pragma unroll
    for (int i = 0; i < 8; ++i) ax[i] = 0ull;
    gemv1(ax, w0x, g_xT, ks * 8, ks * 8 + 8, bcol);

    for (int r = 0; r <= T_; ++r) {
        uint64_t a0[8], a1[8];
#pragma unroll
        for (int i = 0; i < 8; ++i) { a0[i] = ax[i]; a1[i] = 0ull; }

        // fused: layer0 recurrent (w0) + layer1 feed-forward (w1ff), both
        // reading h1[r-1]
        if (r >= 1)
            gemv_pair(a0, a1, w0, w1ff,
                      g_h1 + (size_t)(r - 1) * H_ * B_,
                      ks * 64, ks * 64 + 64, bcol);
        // layer1 recurrent over h2[r-2]
        if (r >= 2)
            gemv1(a1, w1, g_h2 + (size_t)(r - 2) * H_ * B_,
                  ks * 64, ks * 64 + 64, bcol);

        // store partials: gp[l][ks][pair][bcol]
#pragma unroll
        for (int i = 0; i < 8; ++i) {
            gp[((size_t)(0 * 8 + ks) * 8 + i) * B_ + bcol] = a0[i];
            gp[((size_t)(1 * 8 + ks) * 8 + i) * B_ + bcol] = a1[i];
        }
        __syncthreads();

        // gates on warps 0-7; warps 8-15 start next round's x-ff slice
        if (tid < 256) {
            int l = tid >> 7, p = (tid >> 6) & 1, b = tid & 63;
            bool act = l ? (r >= 1) : (r < T_);
            if (act) {
                uint64_t s[4];
#pragma unroll
                for (int g = 0; g < 4; ++g) {
                    int pi = g * 2 + p;
                    uint64_t v = gp[((size_t)(l * 8) * 8 + pi) * B_ + b];
#pragma unroll
                    for (int ss = 1; ss < 8; ++ss)
                        addf2(v, gp[((size_t)(l * 8 + ss) * 8 + pi) * B_ + b]);
                    s[g] = v;
                }
                float2 vi = unpk(s[0]), vf = unpk(s[1]);
                float2 vg = unpk(s[2]), vo = unpk(s[3]);
                const float* bb = bias + l * 16;
                int t = l ? (r - 1) : r;
                float* hout = l ? g_h2 : g_h1;
#pragma unroll
                for (int j2 = 0; j2 < 2; ++j2) {
                    int j = 2 * p + j2;
                    float gi = (j2 ? vi.y : vi.x) + bb[j];
                    float gf = (j2 ? vf.y : vf.x) + bb[4 + j];
                    float gg = (j2 ? vg.y : vg.x) + bb[8 + j];
                    float go = (j2 ? vo.y : vo.x) + bb[12 + j];
                    float si = fast_sigmoid(gi);
                    float sf = fast_sigmoid(gf);
                    float so = fast_sigmoid(go);
                    float tg = fast_tanh(gg);
                    int ci = (l * 4 + j) * 64 + b;
                    float c = sf * cst[ci] + si * tg;
                    cst[ci] = c;
                    hout[(size_t)t * H_ * B_ + (size_t)(j0 + j) * B_ + b]
                        = so * fast_tanh(c);
                }
            }
        } else {
#pragma unroll
            for (int i = 0; i < 8; ++i) ax[i] = 0ull;
            if (r + 1 < T_)
                gemv1(ax, w0x, g_xT + (size_t)(r + 1) * D_ * B_,
                      ks * 8, ks * 8 + 8, bcol);
        }
        __syncthreads();

        // publish round r, then overlap remaining x-ff with the spin
        if (tid == 0) {
            __threadfence();
            atomicAdd(&g_cnt[r], 1);
        }
        if (tid < 256) {
#pragma unroll
            for (int i = 0; i < 8; ++i) ax[i] = 0ull;
            if (r + 1 < T_)
                gemv1(ax, w0x, g_xT + (size_t)(r + 1) * D_ * B_,
                      ks * 8, ks * 8 + 8, bcol);
        }
        if (tid == 0) {
            while (ld_acq(&g_cnt[r]) < NCTA) {}
        }
        __syncthreads();
    }

    // ---- head on CTA 0: logits = h2[:,T-1] @ Wlin^T + blin; log_softmax ----
    if (blockIdx.x == 0) {
        float* hv = (float*)smem;                      // [64][521]
        float* lg = (float*)(smem + OFF_LG);           // [640]
        const float* h2l = g_h2 + (size_t)(T_ - 1) * H_ * B_;
        for (int idx = tid; idx < H_ * B_; idx += NTHR) {
            int k = idx >> 6, b = idx & 63;
            hv[b * HV_STRIDE + k] = h2l[idx];
        }
        __syncthreads();
        int w = wid;                                   // 16 warps x 40 pairs
        for (int pr = w * 40; pr < w * 40 + 40; ++pr) {
            int b = pr / OUT_, o = pr % OUT_;
            float s = 0.f;
            for (int i = lane; i < H_; i += 32)
                s += hv[b * HV_STRIDE + i] * Wlin[(size_t)o * H_ + i];
#pragma unroll
            for (int off = 16; off; off >>= 1)
                s += __shfl_xor_sync(0xffffffffu, s, off);
            if (lane == 0) lg[pr] = s + blin[o];
        }
        __syncthreads();
        if (tid < B_) {
            float m = -1e30f;
#pragma unroll
            for (int q = 0; q < OUT_; ++q) m = fmaxf(m, lg[tid * OUT_ + q]);
            float z = 0.f;
#pragma unroll
            for (int q = 0; q < OUT_; ++q) z += expf(lg[tid * OUT_ + q] - m);
            float lse = m + logf(z);
#pragma unroll
            for (int q = 0; q < OUT_; ++q)
                out[tid * OUT_ + q] = lg[tid * OUT_ + q] - lse;
        }
    }
}

extern "C" void kernel_launch(void* const* d_in, const int* in_sizes, int n_in,
                              void* d_out, int out_size) {
    const float* x    = (const float*)d_in[0];
    const float* Wih0 = (const float*)d_in[1];
    const float* Whh0 = (const float*)d_in[2];
    const float* bih0 = (const float*)d_in[3];
    const float* bhh0 = (const float*)d_in[4];
    const float* Wih1 = (const float*)d_in[5];
    const float* Whh1 = (const float*)d_in[6];
    const float* bih1 = (const float*)d_in[7];
    const float* bhh1 = (const float*)d_in[8];
    const float* Wlin = (const float*)d_in[9];
    const float* blin = (const float*)d_in[10];
    float* out = (float*)d_out;

    cudaFuncSetAttribute(lstm_kernel,
                         cudaFuncAttributeMaxDynamicSharedMemorySize,
                         (int)SMEM_BYTES);

    prep_kernel<<<T_, 256>>>(x);
    lstm_kernel<<<NCTA, NTHR, SMEM_BYTES>>>(Wih0, Whh0, bih0, bhh0,
                                            Wih1, Whh1, bih1, bhh1,
                                            Wlin, blin, out);
}

// round 6
// speedup vs baseline: 2.7900x; 1.2836x over previous
#include <cuda_runtime.h>
#include <cstdint>
#include <math.h>

// ---------------------------------------------------------------------------
// 2-layer LSTM (B=64, T=2048, D=64, H=512) + linear head + log_softmax.
//
// Persistent weight-stationary kernel, layers pipelined: round r = layer0
// step r + layer1 step r-1, one global barrier per round (2049 rounds).
//
// R5 ncu: L1TEX 72% = binder (broadcast LDS of weights). Fix: each lane owns
// TWO batches (one LDG.64), so each LDS.128 weight row-pair feeds 4 FFMA2
// (2 rows x 2 batches) instead of 2 -> LDS wavefronts halved, kernel becomes
// FMA-bound. 16 warps = 16 k-slices; layers computed sequentially per round
// to keep acc regs at 16 f32x2; slice reduction in two stages (hi warps
// store, lo warps RMW) so partials fit in 64 KB.
// ---------------------------------------------------------------------------

namespace {
constexpr int B_   = 64;
constexpr int T_   = 2048;
constexpr int D_   = 64;
constexpr int H_   = 512;
constexpr int OUT_ = 10;
constexpr int NCTA = 128;
constexpr int NTHR = 512;
constexpr int ROWS = 16;                  // gate rows per layer per CTA
constexpr int K0   = H_ + D_;             // layer0: [h1_prev ; x]
constexpr int K1   = H_ + H_;             // layer1: [h2_prev ; h1_t]

constexpr size_t OFF_W0  = 0;                                   // [576][16]
constexpr size_t OFF_W1  = OFF_W0 + (size_t)K0 * ROWS * 4;      //  36864
constexpr size_t OFF_GP0 = OFF_W1 + (size_t)K1 * ROWS * 4;      // 102400
constexpr size_t OFF_GP1 = OFF_GP0 + (size_t)8 * 8 * B_ * 8;    // 135168
constexpr size_t OFF_CST = OFF_GP1 + (size_t)8 * 8 * B_ * 8;    // 167936
constexpr size_t OFF_BIA = OFF_CST + 2048;                      // 169984
constexpr size_t SMEM_BYTES = OFF_BIA + 128;                    // 170112

constexpr int HV_STRIDE = 521;                  // head staging
constexpr size_t OFF_LG = (size_t)B_ * HV_STRIDE * 4;           // 133376
}

// Static device scratch (no runtime allocation).
__device__ float g_h1[(size_t)T_ * H_ * B_];   // layer0 h, [t][unit][b]
__device__ float g_h2[(size_t)T_ * H_ * B_];   // layer1 h, [t][unit][b]
__device__ float g_xT[(size_t)T_ * D_ * B_];   // x transposed, [t][k][b]
__device__ int   g_cnt[T_ + 1];                // per-round arrival counters

__device__ __forceinline__ void ffma2(uint64_t& acc, uint64_t a, uint64_t b) {
    asm("fma.rn.f32x2 %0, %1, %2, %0;" : "+l"(acc) : "l"(a), "l"(b));
}
__device__ __forceinline__ void addf2(uint64_t& acc, uint64_t a) {
    asm("add.rn.f32x2 %0, %0, %1;" : "+l"(acc) : "l"(a));
}
__device__ __forceinline__ uint64_t dup2(float x) {
    uint64_t r;
    asm("mov.b64 %0, {%1, %1};" : "=l"(r) : "f"(x));
    return r;
}
__device__ __forceinline__ float2 unpk(uint64_t v) {
    float2 f;
    asm("mov.b64 {%0, %1}, %2;" : "=f"(f.x), "=f"(f.y) : "l"(v));
    return f;
}
__device__ __forceinline__ int ld_acq(const int* p) {
    int v;
    asm volatile("ld.global.acquire.gpu.b32 %0, [%1];" : "=r"(v) : "l"(p));
    return v;
}
__device__ __forceinline__ float fast_sigmoid(float x) {
    return 1.f / (1.f + __expf(-x));
}
__device__ __forceinline__ float fast_tanh(float x) {
    float a = fabsf(x);
    float t = __expf(-2.f * a);
    float r = (1.f - t) / (1.f + t);
    return copysignf(r, x);
}

// acc{A,B}[p] (+)= W[k][2p..2p+1] * in[k][b2(+1)], k in [kb,ke).
// One LDG.64 per k serves both batches; one LDS.128 serves 4 FFMA2.
__device__ __forceinline__ void gemv2(uint64_t aA[8], uint64_t aB[8],
                                      const float* __restrict__ wsm,
                                      const float* __restrict__ in,
                                      int kb, int ke, int b2) {
#pragma unroll 4
    for (int k = kb; k < ke; ++k) {
        float2 v = *(const float2*)(in + (size_t)k * B_ + b2);
        uint64_t x0 = dup2(v.x);
        uint64_t x1 = dup2(v.y);
        const ulonglong2* wv = (const ulonglong2*)(wsm + (size_t)k * ROWS);
#pragma unroll
        for (int q = 0; q < 4; ++q) {
            ulonglong2 wp = wv[q];
            ffma2(aA[2 * q],     wp.x, x0);
            ffma2(aA[2 * q + 1], wp.y, x0);
            ffma2(aB[2 * q],     wp.x, x1);
            ffma2(aB[2 * q + 1], wp.y, x1);
        }
    }
}

// prep: zero round counters + transpose x[b][t][k] -> g_xT[t][k][b]
__global__ void prep_kernel(const float* __restrict__ x) {
    __shared__ float tile[64][65];
    int t = blockIdx.x;
    if (threadIdx.x == 0) {
        g_cnt[t] = 0;
        if (t == 0) g_cnt[T_] = 0;
    }
    for (int i = threadIdx.x; i < 64 * 64; i += blockDim.x) {
        int b = i >> 6, k = i & 63;
        tile[b][k] = x[(size_t)b * T_ * D_ + (size_t)t * D_ + k];
    }
    __syncthreads();
    for (int i = threadIdx.x; i < 64 * 64; i += blockDim.x) {
        int k = i >> 6, b = i & 63;
        g_xT[(size_t)t * D_ * B_ + (size_t)k * B_ + b] = tile[b][k];
    }
}

__global__ __launch_bounds__(NTHR, 1)
void lstm_kernel(const float* __restrict__ Wih0, const float* __restrict__ Whh0,
                 const float* __restrict__ bih0, const float* __restrict__ bhh0,
                 const float* __restrict__ Wih1, const float* __restrict__ Whh1,
                 const float* __restrict__ bih1, const float* __restrict__ bhh1,
                 const float* __restrict__ Wlin, const float* __restrict__ blin,
                 float* __restrict__ out) {
    extern __shared__ unsigned char smem[];
    float*    w0   = (float*)(smem + OFF_W0);      // [K0][16]
    float*    w1   = (float*)(smem + OFF_W1);      // [K1][16]
    uint64_t* gp0  = (uint64_t*)(smem + OFF_GP0);  // [8 slice][8 pair][64 b]
    uint64_t* gp1  = (uint64_t*)(smem + OFF_GP1);  // [8 slice][8 pair][64 b]
    float*    cst  = (float*)(smem + OFF_CST);     // [2][4][64]
    float*    bias = (float*)(smem + OFF_BIA);     // [2][16]

    const int tid  = threadIdx.x;
    const int lane = tid & 31;
    const int s    = tid >> 5;                     // k-slice 0..15
    const int b2   = 2 * lane;                     // batches b2, b2+1
    const int j0   = blockIdx.x * 4;
    const bool hi  = (s >= 8);
    const int slo  = s & 7;

    // ---- load weights (row r = gate*4 + j; k<H_ -> W_hh else W_ih) ----
    for (int idx = tid; idx < K0 * ROWS; idx += NTHR) {
        int k = idx >> 4, r = idx & 15;
        int row = (r >> 2) * H_ + j0 + (r & 3);
        w0[idx] = (k < H_) ? Whh0[(size_t)row * H_ + k]
                           : Wih0[(size_t)row * D_ + (k - H_)];
    }
    for (int idx = tid; idx < K1 * ROWS; idx += NTHR) {
        int k = idx >> 4, r = idx & 15;
        int row = (r >> 2) * H_ + j0 + (r & 3);
        w1[idx] = (k < H_) ? Whh1[(size_t)row * H_ + k]
                           : Wih1[(size_t)row * H_ + (k - H_)];
    }
    if (tid < 32) {
        int l = tid >> 4, r = tid & 15;
        int row = (r >> 2) * H_ + j0 + (r & 3);
        bias[tid] = l ? (bih1[row] + bhh1[row]) : (bih0[row] + bhh0[row]);
    }
    cst[tid] = 0.f;                                // 512 entries
    __syncthreads();

    const float* w0x  = w0 + (size_t)H_ * ROWS;    // layer0 x-ff rows
    const float* w1ff = w1 + (size_t)H_ * ROWS;    // layer1 h1-ff rows

    for (int r = 0; r <= T_; ++r) {
        uint64_t aA[8], aB[8];

        // ================= layer 0 (step r) =================
#pragma unroll
        for (int i = 0; i < 8; ++i) { aA[i] = 0ull; aB[i] = 0ull; }
        if (r < T_) {
            if (r >= 1)
                gemv2(aA, aB, w0, g_h1 + (size_t)(r - 1) * H_ * B_,
                      s * 32, s * 32 + 32, b2);
            gemv2(aA, aB, w0x, g_xT + (size_t)r * D_ * B_,
                  s * 4, s * 4 + 4, b2);
        }
        if (hi) {
            ulonglong2* d = (ulonglong2*)(gp0 + ((size_t)slo * 8) * B_ + b2);
#pragma unroll
            for (int p = 0; p < 8; ++p)
                d[p * (B_ / 2)] = make_ulonglong2(aA[p], aB[p]);
        }
        __syncthreads();
        if (!hi) {
            ulonglong2* d = (ulonglong2*)(gp0 + ((size_t)slo * 8) * B_ + b2);
#pragma unroll
            for (int p = 0; p < 8; ++p) {
                ulonglong2 o = d[p * (B_ / 2)];
                addf2(aA[p], o.x);
                addf2(aB[p], o.y);
                d[p * (B_ / 2)] = make_ulonglong2(aA[p], aB[p]);
            }
        }

        // ================= layer 1 (step r-1) =================
#pragma unroll
        for (int i = 0; i < 8; ++i) { aA[i] = 0ull; aB[i] = 0ull; }
        if (r >= 1)
            gemv2(aA, aB, w1ff, g_h1 + (size_t)(r - 1) * H_ * B_,
                  s * 32, s * 32 + 32, b2);
        if (r >= 2)
            gemv2(aA, aB, w1, g_h2 + (size_t)(r - 2) * H_ * B_,
                  s * 32, s * 32 + 32, b2);
        if (hi) {
            ulonglong2* d = (ulonglong2*)(gp1 + ((size_t)slo * 8) * B_ + b2);
#pragma unroll
            for (int p = 0; p < 8; ++p)
                d[p * (B_ / 2)] = make_ulonglong2(aA[p], aB[p]);
        }
        __syncthreads();
        if (!hi) {
            ulonglong2* d = (ulonglong2*)(gp1 + ((size_t)slo * 8) * B_ + b2);
#pragma unroll
            for (int p = 0; p < 8; ++p) {
                ulonglong2 o = d[p * (B_ / 2)];
                addf2(aA[p], o.x);
                addf2(aB[p], o.y);
                d[p * (B_ / 2)] = make_ulonglong2(aA[p], aB[p]);
            }
        }
        __syncthreads();

        // ================= gates + state update =================
        if (tid < 256) {
            int l = tid >> 7, p = (tid >> 6) & 1, b = tid & 63;
            bool act = l ? (r >= 1) : (r < T_);
            if (act) {
                const uint64_t* gpl = l ? gp1 : gp0;
                uint64_t sg[4];
#pragma unroll
                for (int g = 0; g < 4; ++g) {
                    int pi = g * 2 + p;
                    uint64_t v = gpl[(size_t)pi * B_ + b];
#pragma unroll
                    for (int ss = 1; ss < 8; ++ss)
                        addf2(v, gpl[((size_t)ss * 8 + pi) * B_ + b]);
                    sg[g] = v;
                }
                float2 vi = unpk(sg[0]), vf = unpk(sg[1]);
                float2 vg = unpk(sg[2]), vo = unpk(sg[3]);
                const float* bb = bias + l * 16;
                int t = l ? (r - 1) : r;
                float* hout = l ? g_h2 : g_h1;
#pragma unroll
                for (int j2 = 0; j2 < 2; ++j2) {
                    int j = 2 * p + j2;
                    float gi = (j2 ? vi.y : vi.x) + bb[j];
                    float gf = (j2 ? vf.y : vf.x) + bb[4 + j];
                    float gg = (j2 ? vg.y : vg.x) + bb[8 + j];
                    float go = (j2 ? vo.y : vo.x) + bb[12 + j];
                    float si = fast_sigmoid(gi);
                    float sf = fast_sigmoid(gf);
                    float so = fast_sigmoid(go);
                    float tg = fast_tanh(gg);
                    int ci = (l * 4 + j) * 64 + b;
                    float c = sf * cst[ci] + si * tg;
                    cst[ci] = c;
                    hout[(size_t)t * H_ * B_ + (size_t)(j0 + j) * B_ + b]
                        = so * fast_tanh(c);
                }
            }
        }
        __syncthreads();

        // ================= global barrier for round r =================
        if (tid == 0) {
            __threadfence();
            atomicAdd(&g_cnt[r], 1);
            while (ld_acq(&g_cnt[r]) < NCTA) {}
        }
        __syncthreads();
    }

    // ---- head on CTA 0: logits = h2[:,T-1] @ Wlin^T + blin; log_softmax ----
    if (blockIdx.x == 0) {
        float* hv = (float*)smem;                      // [64][521]
        float* lg = (float*)(smem + OFF_LG);           // [640]
        const float* h2l = g_h2 + (size_t)(T_ - 1) * H_ * B_;
        for (int idx = tid; idx < H_ * B_; idx += NTHR) {
            int k = idx >> 6, b = idx & 63;
            hv[b * HV_STRIDE + k] = h2l[idx];
        }
        __syncthreads();
        for (int pr = s * 40; pr < s * 40 + 40; ++pr) {
            int b = pr / OUT_, o = pr % OUT_;
            float sum = 0.f;
            for (int i = lane; i < H_; i += 32)
                sum += hv[b * HV_STRIDE + i] * Wlin[(size_t)o * H_ + i];
#pragma unroll
            for (int off = 16; off; off >>= 1)
                sum += __shfl_xor_sync(0xffffffffu, sum, off);
            if (lane == 0) lg[pr] = sum + blin[o];
        }
        __syncthreads();
        if (tid < B_) {
            float m = -1e30f;
#pragma unroll
            for (int q = 0; q < OUT_; ++q) m = fmaxf(m, lg[tid * OUT_ + q]);
            float z = 0.f;
#pragma unroll
            for (int q = 0; q < OUT_; ++q) z += expf(lg[tid * OUT_ + q] - m);
            float lse = m + logf(z);
#pragma unroll
            for (int q = 0; q < OUT_; ++q)
                out[tid * OUT_ + q] = lg[tid * OUT_ + q] - lse;
        }
    }
}

extern "C" void kernel_launch(void* const* d_in, const int* in_sizes, int n_in,
                              void* d_out, int out_size) {
    const float* x    = (const float*)d_in[0];
    const float* Wih0 = (const float*)d_in[1];
    const float* Whh0 = (const float*)d_in[2];
    const float* bih0 = (const float*)d_in[3];
    const float* bhh0 = (const float*)d_in[4];
    const float* Wih1 = (const float*)d_in[5];
    const float* Whh1 = (const float*)d_in[6];
    const float* bih1 = (const float*)d_in[7];
    const float* bhh1 = (const float*)d_in[8];
    const float* Wlin = (const float*)d_in[9];
    const float* blin = (const float*)d_in[10];
    float* out = (float*)d_out;

    cudaFuncSetAttribute(lstm_kernel,
                         cudaFuncAttributeMaxDynamicSharedMemorySize,
                         (int)SMEM_BYTES);

    prep_kernel<<<T_, 256>>>(x);
    lstm_kernel<<<NCTA, NTHR, SMEM_BYTES>>>(Wih0, Whh0, bih0, bhh0,
                                            Wih1, Whh1, bih1, bhh1,
                                            Wlin, blin, out);
}